// round 2
// baseline (speedup 1.0000x reference)
#include <cuda_runtime.h>
#include <cuda_fp16.h>
#include <cstdint>
#include <cstddef>

// Problem dims: y[b,m,n] = sum_k x[b,m,k] w[k,n]; flatten b,m -> M
#define MDIM 8192
#define KDIM 4096
#define NDIM 4096

// GEMM tiling (mma.sync path — tcgen05 unavailable on plain sm_103 target)
#define BM 128
#define BN 128
#define BK 32
#define STAGES 4
#define KT (KDIM / BK)       // 128
#define THREADS 256

#define LDA 40               // fp16 elems per A smem row (32 + 8 pad)
#define LDB 136              // fp16 elems per B smem row (128 + 8 pad)
#define A_TILE_B (BM * LDA * 2)   // 10240
#define B_TILE_B (BK * LDB * 2)   // 8704
#define STAGE_B (A_TILE_B + B_TILE_B)  // 18944
#define SMEM_B (STAGES * STAGE_B)      // 75776

// fp16 scratch (allocation-free rule: __device__ globals)
__device__ __half g_xh[(size_t)MDIM * KDIM];  // 67 MB
__device__ __half g_wh[(size_t)KDIM * NDIM];  // 33.5 MB

static __device__ __forceinline__ uint32_t smem_u32(const void* p) {
    uint32_t a;
    asm("{ .reg .u64 t; cvta.to.shared.u64 t, %1; cvt.u32.u64 %0, t; }"
        : "=r"(a) : "l"(p));
    return a;
}

#define CP_ASYNC16(dst, src) \
    asm volatile("cp.async.cg.shared.global [%0], [%1], 16;" :: "r"(dst), "l"(src))
#define CP_COMMIT() asm volatile("cp.async.commit_group;" ::: "memory")
#define CP_WAIT(n)  asm volatile("cp.async.wait_group %0;" :: "n"(n) : "memory")

#define LDMATRIX_X4(r0, r1, r2, r3, addr)                                  \
    asm volatile("ldmatrix.sync.aligned.m8n8.x4.shared.b16 "               \
                 "{%0,%1,%2,%3}, [%4];"                                    \
                 : "=r"(r0), "=r"(r1), "=r"(r2), "=r"(r3) : "r"(addr))

#define LDMATRIX_X2_T(r0, r1, addr)                                        \
    asm volatile("ldmatrix.sync.aligned.m8n8.x2.trans.shared.b16 "         \
                 "{%0,%1}, [%2];"                                          \
                 : "=r"(r0), "=r"(r1) : "r"(addr))

#define MMA16816(d, a, b)                                                  \
    asm volatile("mma.sync.aligned.m16n8k16.row.col.f32.f16.f16.f32 "      \
                 "{%0,%1,%2,%3}, {%4,%5,%6,%7}, {%8,%9}, {%0,%1,%2,%3};"   \
                 : "+f"((d)[0]), "+f"((d)[1]), "+f"((d)[2]), "+f"((d)[3])  \
                 : "r"((a)[0]), "r"((a)[1]), "r"((a)[2]), "r"((a)[3]),     \
                   "r"((b)[0]), "r"((b)[1]))

// ---------------------------------------------------------------------------
// prep: fp32 -> fp16 conversion (w is ternary -> exact; x |max|<6 -> in range)
// ---------------------------------------------------------------------------
__global__ void cvt_kernel(const float4* __restrict__ src, __half* __restrict__ dst) {
    size_t i = (size_t)blockIdx.x * blockDim.x + threadIdx.x;  // grid exact
    float4 v = src[i];
    __half2 h0 = __floats2half2_rn(v.x, v.y);
    __half2 h1 = __floats2half2_rn(v.z, v.w);
    uint2 o;
    o.x = *reinterpret_cast<uint32_t*>(&h0);
    o.y = *reinterpret_cast<uint32_t*>(&h1);
    reinterpret_cast<uint2*>(dst)[i] = o;
}

// ---------------------------------------------------------------------------
// GEMM: 128x128x32 CTA, 8 warps (2 m x 4 n), warp tile 64x32, 4-stage cp.async
// ---------------------------------------------------------------------------
__global__ void __launch_bounds__(THREADS, 2) gemm_kernel(float* __restrict__ out) {
    extern __shared__ char smem_raw[];
    const uint32_t smem = smem_u32(smem_raw);

    const int tid = threadIdx.x;
    const int lane = tid & 31;
    const int wid = tid >> 5;
    const int warp_m = wid & 1;   // 0..1
    const int warp_n = wid >> 1;  // 0..3

    const int m0 = blockIdx.y * BM;
    const int n0 = blockIdx.x * BN;

    // ---- cp.async load helper (computed per thread once) ----
    // A tile: 512 chunks of 16B; chunk c -> row c/4, col-chunk c%4
    const int ca0 = tid;             // chunks tid, tid+256
    const int a_row0 = ca0 >> 2, a_ch0 = ca0 & 3;
    const int a_row1 = (ca0 + 256) >> 2, a_ch1 = (ca0 + 256) & 3;
    // B tile: 512 chunks; chunk c -> row c/16, col-chunk c%16
    const int b_row0 = tid >> 4, b_ch0 = tid & 15;
    const int b_row1 = (tid + 256) >> 4, b_ch1 = (tid + 256) & 15;

    const __half* gA = g_xh + (size_t)m0 * KDIM;
    const __half* gB = g_wh + n0;

    uint32_t sA_d0 = smem + (uint32_t)(a_row0 * LDA + a_ch0 * 8) * 2;
    uint32_t sA_d1 = smem + (uint32_t)(a_row1 * LDA + a_ch1 * 8) * 2;
    uint32_t sB_d0 = smem + A_TILE_B + (uint32_t)(b_row0 * LDB + b_ch0 * 8) * 2;
    uint32_t sB_d1 = smem + A_TILE_B + (uint32_t)(b_row1 * LDB + b_ch1 * 8) * 2;

#define ISSUE_STAGE(s, kt_)                                                         \
    do {                                                                            \
        const uint32_t sb = (uint32_t)(s) * STAGE_B;                                \
        const int kb = (kt_) * BK;                                                  \
        CP_ASYNC16(sA_d0 + sb, gA + (size_t)a_row0 * KDIM + kb + a_ch0 * 8);        \
        CP_ASYNC16(sA_d1 + sb, gA + (size_t)a_row1 * KDIM + kb + a_ch1 * 8);        \
        CP_ASYNC16(sB_d0 + sb, gB + (size_t)(kb + b_row0) * NDIM + b_ch0 * 8);      \
        CP_ASYNC16(sB_d1 + sb, gB + (size_t)(kb + b_row1) * NDIM + b_ch1 * 8);      \
    } while (0)

    // ---- fragment base addresses ----
    // A (x4): lanes 0-15 rows, lanes 16-31 rows with col +8
    const uint32_t a_frag_base =
        smem + (uint32_t)((warp_m * 64 + (lane & 15)) * LDA + (lane >> 4) * 8) * 2;
    // B (x2.trans): lanes 0-15 -> rows kk+lane at col n-block
    const uint32_t b_frag_base =
        smem + A_TILE_B + (uint32_t)((lane & 15) * LDB + warp_n * 32) * 2;

    float acc[4][4][4];
#pragma unroll
    for (int mi = 0; mi < 4; ++mi)
#pragma unroll
        for (int ni = 0; ni < 4; ++ni)
#pragma unroll
            for (int q = 0; q < 4; ++q) acc[mi][ni][q] = 0.f;

    // ---- prologue: fill STAGES-1 stages ----
#pragma unroll
    for (int s = 0; s < STAGES - 1; ++s) {
        ISSUE_STAGE(s, s);
        CP_COMMIT();
    }

    // ---- mainloop ----
    for (int kt = 0; kt < KT; ++kt) {
        CP_WAIT(STAGES - 2);
        __syncthreads();

        // prefetch stage kt+STAGES-1 into slot just freed
        if (kt + STAGES - 1 < KT) {
            ISSUE_STAGE((kt + STAGES - 1) & (STAGES - 1), kt + STAGES - 1);
        }
        CP_COMMIT();

        const uint32_t sb = (uint32_t)(kt & (STAGES - 1)) * STAGE_B;
        const uint32_t aB = a_frag_base + sb;
        const uint32_t bB = b_frag_base + sb;

#pragma unroll
        for (int kk = 0; kk < 2; ++kk) {
            uint32_t a[4][4], b[4][2];
#pragma unroll
            for (int mi = 0; mi < 4; ++mi)
                LDMATRIX_X4(a[mi][0], a[mi][1], a[mi][2], a[mi][3],
                            aB + (uint32_t)(mi * 16 * LDA + kk * 16) * 2);
#pragma unroll
            for (int ni = 0; ni < 4; ++ni)
                LDMATRIX_X2_T(b[ni][0], b[ni][1],
                              bB + (uint32_t)(kk * 16 * LDB + ni * 8) * 2);
#pragma unroll
            for (int mi = 0; mi < 4; ++mi)
#pragma unroll
                for (int ni = 0; ni < 4; ++ni)
                    MMA16816(acc[mi][ni], a[mi], b[ni]);
        }
    }

    // ---- epilogue: direct fp32 stores ----
    const int mg = m0 + warp_m * 64 + (lane >> 2);
    const int ng = n0 + warp_n * 32 + (lane & 3) * 2;
#pragma unroll
    for (int mi = 0; mi < 4; ++mi) {
#pragma unroll
        for (int ni = 0; ni < 4; ++ni) {
            float* p0 = out + (size_t)(mg + mi * 16) * NDIM + ng + ni * 8;
            float* p1 = p0 + 8 * NDIM;
            *reinterpret_cast<float2*>(p0) = make_float2(acc[mi][ni][0], acc[mi][ni][1]);
            *reinterpret_cast<float2*>(p1) = make_float2(acc[mi][ni][2], acc[mi][ni][3]);
        }
    }
}

// ---------------------------------------------------------------------------
extern "C" void kernel_launch(void* const* d_in, const int* in_sizes, int n_in,
                              void* d_out, int out_size) {
    const float* x = (const float*)d_in[0];  // (4, 2048, 4096) fp32
    const float* w = (const float*)d_in[1];  // (4096, 4096) fp32 ternary
    float* out = (float*)d_out;              // (4, 2048, 4096) fp32

    __half* xh;
    __half* wh;
    cudaGetSymbolAddress((void**)&xh, g_xh);
    cudaGetSymbolAddress((void**)&wh, g_wh);

    cvt_kernel<<<(int)((size_t)MDIM * KDIM / 4 / 256), 256>>>(
        reinterpret_cast<const float4*>(x), xh);
    cvt_kernel<<<(int)((size_t)KDIM * NDIM / 4 / 256), 256>>>(
        reinterpret_cast<const float4*>(w), wh);

    cudaFuncSetAttribute(gemm_kernel, cudaFuncAttributeMaxDynamicSharedMemorySize,
                         SMEM_B);
    dim3 grid(NDIM / BN, MDIM / BM);  // (32, 64)
    gemm_kernel<<<grid, THREADS, SMEM_B>>>(out);
}

// round 3
// speedup vs baseline: 1.0320x; 1.0320x over previous
#include <cuda_runtime.h>
#include <cuda_fp16.h>
#include <cstdint>
#include <cstddef>

// Problem dims: y[b,m,n] = sum_k x[b,m,k] w[k,n]; flatten b,m -> M
#define MDIM 8192
#define KDIM 4096
#define NDIM 4096

// GEMM tiling: CTA 128x256x64, 8 warps, warp tile 64x64, 3-stage cp.async
#define BM 128
#define BN 256
#define BK 64
#define STAGES 3
#define KT (KDIM / BK)  // 64
#define THREADS 256

#define LDA 72   // 64 + 8 pad (fp16 elems per A smem row)
#define LDB 264  // 256 + 8 pad
#define A_TILE_B (BM * LDA * 2)        // 18432
#define B_TILE_B (BK * LDB * 2)        // 33792
#define STAGE_B (A_TILE_B + B_TILE_B)  // 52224
#define SMEM_B (STAGES * STAGE_B)      // 156672

// fp16 scratch (allocation-free rule: __device__ globals)
__device__ __half g_xh[(size_t)MDIM * KDIM];  // 67 MB
__device__ __half g_wh[(size_t)KDIM * NDIM];  // 33.5 MB

static __device__ __forceinline__ uint32_t smem_u32(const void* p) {
    uint32_t a;
    asm("{ .reg .u64 t; cvta.to.shared.u64 t, %1; cvt.u32.u64 %0, t; }"
        : "=r"(a) : "l"(p));
    return a;
}

#define CP_ASYNC16(dst, src) \
    asm volatile("cp.async.cg.shared.global [%0], [%1], 16;" :: "r"(dst), "l"(src))
#define CP_COMMIT() asm volatile("cp.async.commit_group;" ::: "memory")
#define CP_WAIT(n)  asm volatile("cp.async.wait_group %0;" :: "n"(n) : "memory")

#define LDMATRIX_X4(r0, r1, r2, r3, addr)                                  \
    asm volatile("ldmatrix.sync.aligned.m8n8.x4.shared.b16 "               \
                 "{%0,%1,%2,%3}, [%4];"                                    \
                 : "=r"(r0), "=r"(r1), "=r"(r2), "=r"(r3) : "r"(addr))

#define LDMATRIX_X4_T(r0, r1, r2, r3, addr)                                \
    asm volatile("ldmatrix.sync.aligned.m8n8.x4.trans.shared.b16 "         \
                 "{%0,%1,%2,%3}, [%4];"                                    \
                 : "=r"(r0), "=r"(r1), "=r"(r2), "=r"(r3) : "r"(addr))

#define MMA16816(d, a, b0, b1)                                             \
    asm volatile("mma.sync.aligned.m16n8k16.row.col.f32.f16.f16.f32 "      \
                 "{%0,%1,%2,%3}, {%4,%5,%6,%7}, {%8,%9}, {%0,%1,%2,%3};"   \
                 : "+f"((d)[0]), "+f"((d)[1]), "+f"((d)[2]), "+f"((d)[3])  \
                 : "r"((a)[0]), "r"((a)[1]), "r"((a)[2]), "r"((a)[3]),     \
                   "r"(b0), "r"(b1))

// ---------------------------------------------------------------------------
// prep: fp32 -> fp16 (w is ternary -> exact; |x| < 6 -> in fp16 range)
// ---------------------------------------------------------------------------
__global__ void cvt_kernel(const float4* __restrict__ src, __half* __restrict__ dst) {
    size_t i = (size_t)blockIdx.x * blockDim.x + threadIdx.x;  // grid exact
    float4 v = src[i];
    __half2 h0 = __floats2half2_rn(v.x, v.y);
    __half2 h1 = __floats2half2_rn(v.z, v.w);
    uint2 o;
    o.x = *reinterpret_cast<uint32_t*>(&h0);
    o.y = *reinterpret_cast<uint32_t*>(&h1);
    reinterpret_cast<uint2*>(dst)[i] = o;
}

// ---------------------------------------------------------------------------
// GEMM
// ---------------------------------------------------------------------------
__global__ void __launch_bounds__(THREADS, 1) gemm_kernel(float* __restrict__ out) {
    extern __shared__ char smem_raw[];
    const uint32_t smem = smem_u32(smem_raw);

    const int tid = threadIdx.x;
    const int lane = tid & 31;
    const int wid = tid >> 5;
    const int warp_m = wid & 1;   // 0..1
    const int warp_n = wid >> 1;  // 0..3

    const int m0 = blockIdx.y * BM;
    const int n0 = blockIdx.x * BN;

    const __half* gA = g_xh + (size_t)m0 * KDIM;
    const __half* gB = g_wh + n0;

    // ---- cp.async dest addresses (A: 1024 chunks/4 per thread; B: 2048/8) ----
    uint32_t sA_dst[4];
    const __half* gA_src[4];
#pragma unroll
    for (int i = 0; i < 4; ++i) {
        int c = tid + i * THREADS;
        int row = c >> 3, ch = c & 7;
        sA_dst[i] = smem + (uint32_t)(row * LDA + ch * 8) * 2;
        gA_src[i] = gA + (size_t)row * KDIM + ch * 8;
    }
    uint32_t sB_dst[8];
    const __half* gB_src[8];
#pragma unroll
    for (int i = 0; i < 8; ++i) {
        int c = tid + i * THREADS;
        int row = c >> 5, ch = c & 31;
        sB_dst[i] = smem + A_TILE_B + (uint32_t)(row * LDB + ch * 8) * 2;
        gB_src[i] = gB + (size_t)row * NDIM + ch * 8;
    }

#define ISSUE_STAGE(slot, kt_)                                              \
    do {                                                                    \
        const uint32_t sb = (uint32_t)(slot) * STAGE_B;                     \
        const size_t kb = (size_t)(kt_) * BK;                               \
        _Pragma("unroll")                                                   \
        for (int i = 0; i < 4; ++i)                                         \
            CP_ASYNC16(sA_dst[i] + sb, gA_src[i] + kb);                     \
        _Pragma("unroll")                                                   \
        for (int i = 0; i < 8; ++i)                                         \
            CP_ASYNC16(sB_dst[i] + sb, gB_src[i] + kb * NDIM);              \
    } while (0)

    // ---- fragment base addresses ----
    // A x4: lane 0-15 -> rows, lane>>4 -> col +8 (within a 16-col k-slab)
    const uint32_t a_frag =
        smem + (uint32_t)((warp_m * 64 + (lane & 15)) * LDA + (lane >> 4) * 8) * 2;
    // B x4.trans: lane 0-15 -> k-rows, lane>>4 -> n col +8 ; covers 16k x 16n
    const uint32_t b_frag =
        smem + A_TILE_B +
        (uint32_t)((lane & 15) * LDB + warp_n * 64 + (lane >> 4) * 8) * 2;

    float acc[4][8][4];
#pragma unroll
    for (int mi = 0; mi < 4; ++mi)
#pragma unroll
        for (int ni = 0; ni < 8; ++ni)
#pragma unroll
            for (int q = 0; q < 4; ++q) acc[mi][ni][q] = 0.f;

    // ---- prologue ----
#pragma unroll
    for (int s = 0; s < STAGES - 1; ++s) {
        ISSUE_STAGE(s, s);
        CP_COMMIT();
    }

    // ---- mainloop ----
    int s_cur = 0;
    int s_nxt = STAGES - 1;
    for (int kt = 0; kt < KT; ++kt) {
        CP_WAIT(STAGES - 2);
        __syncthreads();

        if (kt + STAGES - 1 < KT) ISSUE_STAGE(s_nxt, kt + STAGES - 1);
        CP_COMMIT();

        const uint32_t sb = (uint32_t)s_cur * STAGE_B;
        const uint32_t aB = a_frag + sb;
        const uint32_t bB = b_frag + sb;

#pragma unroll
        for (int kk = 0; kk < 4; ++kk) {
            uint32_t a[4][4], b[4][4];
#pragma unroll
            for (int mi = 0; mi < 4; ++mi)
                LDMATRIX_X4(a[mi][0], a[mi][1], a[mi][2], a[mi][3],
                            aB + (uint32_t)(mi * 16 * LDA + kk * 16) * 2);
#pragma unroll
            for (int nj = 0; nj < 4; ++nj)
                LDMATRIX_X4_T(b[nj][0], b[nj][1], b[nj][2], b[nj][3],
                              bB + (uint32_t)(kk * 16 * LDB + nj * 16) * 2);
            // b[nj] = {b0(n+0), b1(n+0), b0(n+8), b1(n+8)} for 16 n-cols
#pragma unroll
            for (int mi = 0; mi < 4; ++mi)
#pragma unroll
                for (int nj = 0; nj < 4; ++nj) {
                    MMA16816(acc[mi][2 * nj + 0], a[mi], b[nj][0], b[nj][1]);
                    MMA16816(acc[mi][2 * nj + 1], a[mi], b[nj][2], b[nj][3]);
                }
        }
        if (++s_cur == STAGES) s_cur = 0;
        if (++s_nxt == STAGES) s_nxt = 0;
    }

    // ---- epilogue: direct fp32 stores ----
    const int mg = m0 + warp_m * 64 + (lane >> 2);
    const int ng = n0 + warp_n * 64 + (lane & 3) * 2;
#pragma unroll
    for (int mi = 0; mi < 4; ++mi) {
#pragma unroll
        for (int ni = 0; ni < 8; ++ni) {
            float* p0 = out + (size_t)(mg + mi * 16) * NDIM + ng + ni * 8;
            float* p1 = p0 + 8 * NDIM;
            *reinterpret_cast<float2*>(p0) = make_float2(acc[mi][ni][0], acc[mi][ni][1]);
            *reinterpret_cast<float2*>(p1) = make_float2(acc[mi][ni][2], acc[mi][ni][3]);
        }
    }
}

// ---------------------------------------------------------------------------
extern "C" void kernel_launch(void* const* d_in, const int* in_sizes, int n_in,
                              void* d_out, int out_size) {
    const float* x = (const float*)d_in[0];  // (4, 2048, 4096) fp32
    const float* w = (const float*)d_in[1];  // (4096, 4096) fp32 ternary
    float* out = (float*)d_out;              // (4, 2048, 4096) fp32

    __half* xh;
    __half* wh;
    cudaGetSymbolAddress((void**)&xh, g_xh);
    cudaGetSymbolAddress((void**)&wh, g_wh);

    cvt_kernel<<<(int)((size_t)MDIM * KDIM / 4 / 256), 256>>>(
        reinterpret_cast<const float4*>(x), xh);
    cvt_kernel<<<(int)((size_t)KDIM * NDIM / 4 / 256), 256>>>(
        reinterpret_cast<const float4*>(w), wh);

    cudaFuncSetAttribute(gemm_kernel, cudaFuncAttributeMaxDynamicSharedMemorySize,
                         SMEM_B);
    dim3 grid(NDIM / BN, MDIM / BM);  // (16, 64)
    gemm_kernel<<<grid, THREADS, SMEM_B>>>(out);
}

// round 4
// speedup vs baseline: 1.0338x; 1.0017x over previous
#include <cuda_runtime.h>
#include <cuda_fp16.h>
#include <cstdint>
#include <cstddef>

// Problem dims: y[b,m,n] = sum_k x[b,m,k] w[k,n]; flatten b,m -> M
#define MDIM 8192
#define KDIM 4096
#define NDIM 4096

// GEMM tiling: CTA 128x256x64, 8 warps, warp tile 64x64, 3-stage cp.async
#define BM 128
#define BN 256
#define BK 64
#define STAGES 3
#define KT (KDIM / BK)  // 64
#define THREADS 256

#define LDA 72   // 64 + 8 pad (fp16 elems per A smem row)
#define LDB 264  // 256 + 8 pad
#define A_TILE_B (BM * LDA * 2)        // 18432
#define B_TILE_B (BK * LDB * 2)        // 33792
#define STAGE_B (A_TILE_B + B_TILE_B)  // 52224
#define SMEM_B (STAGES * STAGE_B)      // 156672

// fp16 scratch (allocation-free rule: __device__ globals)
__device__ __half g_xh[(size_t)MDIM * KDIM];  // 67 MB
__device__ __half g_wh[(size_t)KDIM * NDIM];  // 33.5 MB

static __device__ __forceinline__ uint32_t smem_u32(const void* p) {
    uint32_t a;
    asm("{ .reg .u64 t; cvta.to.shared.u64 t, %1; cvt.u32.u64 %0, t; }"
        : "=r"(a) : "l"(p));
    return a;
}

#define CP_ASYNC16(dst, src) \
    asm volatile("cp.async.cg.shared.global [%0], [%1], 16;" :: "r"(dst), "l"(src))
#define CP_COMMIT() asm volatile("cp.async.commit_group;" ::: "memory")
#define CP_WAIT(n)  asm volatile("cp.async.wait_group %0;" :: "n"(n) : "memory")

#define LDMATRIX_X4(r0, r1, r2, r3, addr)                                  \
    asm volatile("ldmatrix.sync.aligned.m8n8.x4.shared.b16 "               \
                 "{%0,%1,%2,%3}, [%4];"                                    \
                 : "=r"(r0), "=r"(r1), "=r"(r2), "=r"(r3) : "r"(addr))

#define LDMATRIX_X4_T(r0, r1, r2, r3, addr)                                \
    asm volatile("ldmatrix.sync.aligned.m8n8.x4.trans.shared.b16 "         \
                 "{%0,%1,%2,%3}, [%4];"                                    \
                 : "=r"(r0), "=r"(r1), "=r"(r2), "=r"(r3) : "r"(addr))

#define MMA16816(d, a, b0, b1)                                             \
    asm volatile("mma.sync.aligned.m16n8k16.row.col.f32.f16.f16.f32 "      \
                 "{%0,%1,%2,%3}, {%4,%5,%6,%7}, {%8,%9}, {%0,%1,%2,%3};"   \
                 : "+f"((d)[0]), "+f"((d)[1]), "+f"((d)[2]), "+f"((d)[3])  \
                 : "r"((a)[0]), "r"((a)[1]), "r"((a)[2]), "r"((a)[3]),     \
                   "r"(b0), "r"(b1))

// ---------------------------------------------------------------------------
// prep: fused fp32 -> fp16 for both x and w (one launch)
// ---------------------------------------------------------------------------
#define XCHUNKS ((size_t)MDIM * KDIM / 4)  // 8388608 float4s
#define WCHUNKS ((size_t)KDIM * NDIM / 4)  // 4194304 float4s

__global__ void cvt_both_kernel(const float4* __restrict__ x4,
                                const float4* __restrict__ w4) {
    size_t i = (size_t)blockIdx.x * blockDim.x + threadIdx.x;
    const float4* src;
    uint2* dst;
    if (i < XCHUNKS) {
        src = x4 + i;
        dst = reinterpret_cast<uint2*>(g_xh) + i;
    } else {
        src = w4 + (i - XCHUNKS);
        dst = reinterpret_cast<uint2*>(g_wh) + (i - XCHUNKS);
    }
    float4 v = *src;
    __half2 h0 = __floats2half2_rn(v.x, v.y);
    __half2 h1 = __floats2half2_rn(v.z, v.w);
    uint2 o;
    o.x = *reinterpret_cast<uint32_t*>(&h0);
    o.y = *reinterpret_cast<uint32_t*>(&h1);
    *dst = o;
}

// ---------------------------------------------------------------------------
// GEMM with register double-buffered fragments
// ---------------------------------------------------------------------------
__global__ void __launch_bounds__(THREADS, 1) gemm_kernel(float* __restrict__ out) {
    extern __shared__ char smem_raw[];
    const uint32_t smem = smem_u32(smem_raw);

    const int tid = threadIdx.x;
    const int lane = tid & 31;
    const int wid = tid >> 5;
    const int warp_m = wid & 1;   // 0..1
    const int warp_n = wid >> 1;  // 0..3

    const int m0 = blockIdx.y * BM;
    const int n0 = blockIdx.x * BN;

    const __half* gA = g_xh + (size_t)m0 * KDIM;
    const __half* gB = g_wh + n0;

    // ---- cp.async dest addresses ----
    uint32_t sA_dst[4];
    const __half* gA_src[4];
#pragma unroll
    for (int i = 0; i < 4; ++i) {
        int c = tid + i * THREADS;
        int row = c >> 3, ch = c & 7;
        sA_dst[i] = smem + (uint32_t)(row * LDA + ch * 8) * 2;
        gA_src[i] = gA + (size_t)row * KDIM + ch * 8;
    }
    uint32_t sB_dst[8];
    const __half* gB_src[8];
#pragma unroll
    for (int i = 0; i < 8; ++i) {
        int c = tid + i * THREADS;
        int row = c >> 5, ch = c & 31;
        sB_dst[i] = smem + A_TILE_B + (uint32_t)(row * LDB + ch * 8) * 2;
        gB_src[i] = gB + (size_t)row * NDIM + ch * 8;
    }

#define ISSUE_STAGE(slot, kt_)                                              \
    do {                                                                    \
        const uint32_t sb = (uint32_t)(slot) * STAGE_B;                     \
        const size_t kb = (size_t)(kt_) * BK;                               \
        _Pragma("unroll")                                                   \
        for (int i = 0; i < 4; ++i)                                         \
            CP_ASYNC16(sA_dst[i] + sb, gA_src[i] + kb);                     \
        _Pragma("unroll")                                                   \
        for (int i = 0; i < 8; ++i)                                         \
            CP_ASYNC16(sB_dst[i] + sb, gB_src[i] + kb * NDIM);              \
    } while (0)

    // ---- fragment base addresses ----
    const uint32_t a_frag =
        smem + (uint32_t)((warp_m * 64 + (lane & 15)) * LDA + (lane >> 4) * 8) * 2;
    const uint32_t b_frag =
        smem + A_TILE_B +
        (uint32_t)((lane & 15) * LDB + warp_n * 64 + (lane >> 4) * 8) * 2;

    // fragment double buffers
    uint32_t a[2][4][4], b[2][4][4];

#define LOAD_FRAGS(buf, aB, bB, kk)                                         \
    do {                                                                    \
        _Pragma("unroll")                                                   \
        for (int mi = 0; mi < 4; ++mi)                                      \
            LDMATRIX_X4(a[buf][mi][0], a[buf][mi][1], a[buf][mi][2],        \
                        a[buf][mi][3],                                      \
                        (aB) + (uint32_t)(mi * 16 * LDA + (kk) * 16) * 2);  \
        _Pragma("unroll")                                                   \
        for (int nj = 0; nj < 4; ++nj)                                      \
            LDMATRIX_X4_T(b[buf][nj][0], b[buf][nj][1], b[buf][nj][2],      \
                          b[buf][nj][3],                                    \
                          (bB) + (uint32_t)((kk) * 16 * LDB + nj * 16) * 2);\
    } while (0)

#define DO_MMAS(buf)                                                        \
    do {                                                                    \
        _Pragma("unroll")                                                   \
        for (int mi = 0; mi < 4; ++mi)                                      \
            _Pragma("unroll")                                               \
            for (int nj = 0; nj < 4; ++nj) {                                \
                MMA16816(acc[mi][2 * nj + 0], a[buf][mi], b[buf][nj][0],    \
                         b[buf][nj][1]);                                    \
                MMA16816(acc[mi][2 * nj + 1], a[buf][mi], b[buf][nj][2],    \
                         b[buf][nj][3]);                                    \
            }                                                               \
    } while (0)

    float acc[4][8][4];
#pragma unroll
    for (int mi = 0; mi < 4; ++mi)
#pragma unroll
        for (int ni = 0; ni < 8; ++ni)
#pragma unroll
            for (int q = 0; q < 4; ++q) acc[mi][ni][q] = 0.f;

    // ---- prologue ----
#pragma unroll
    for (int s = 0; s < STAGES - 1; ++s) {
        ISSUE_STAGE(s, s);
        CP_COMMIT();
    }

    // ---- mainloop ----
    int s_cur = 0;
    int s_nxt = STAGES - 1;
    for (int kt = 0; kt < KT; ++kt) {
        CP_WAIT(STAGES - 2);
        __syncthreads();

        if (kt + STAGES - 1 < KT) ISSUE_STAGE(s_nxt, kt + STAGES - 1);
        CP_COMMIT();

        const uint32_t sb = (uint32_t)s_cur * STAGE_B;
        const uint32_t aB = a_frag + sb;
        const uint32_t bB = b_frag + sb;

        // kk-pipelined: load kk+1 fragments while issuing kk MMAs
        LOAD_FRAGS(0, aB, bB, 0);
#pragma unroll
        for (int kk = 0; kk < 4; ++kk) {
            if (kk < 3) LOAD_FRAGS((kk + 1) & 1, aB, bB, kk + 1);
            DO_MMAS(kk & 1);
        }
        if (++s_cur == STAGES) s_cur = 0;
        if (++s_nxt == STAGES) s_nxt = 0;
    }

    // ---- epilogue: direct fp32 stores ----
    const int mg = m0 + warp_m * 64 + (lane >> 2);
    const int ng = n0 + warp_n * 64 + (lane & 3) * 2;
#pragma unroll
    for (int mi = 0; mi < 4; ++mi) {
#pragma unroll
        for (int ni = 0; ni < 8; ++ni) {
            float* p0 = out + (size_t)(mg + mi * 16) * NDIM + ng + ni * 8;
            float* p1 = p0 + 8 * NDIM;
            *reinterpret_cast<float2*>(p0) = make_float2(acc[mi][ni][0], acc[mi][ni][1]);
            *reinterpret_cast<float2*>(p1) = make_float2(acc[mi][ni][2], acc[mi][ni][3]);
        }
    }
}

// ---------------------------------------------------------------------------
extern "C" void kernel_launch(void* const* d_in, const int* in_sizes, int n_in,
                              void* d_out, int out_size) {
    const float* x = (const float*)d_in[0];  // (4, 2048, 4096) fp32
    const float* w = (const float*)d_in[1];  // (4096, 4096) fp32 ternary
    float* out = (float*)d_out;              // (4, 2048, 4096) fp32

    // fused conversion: one launch covers x and w
    size_t total_chunks = XCHUNKS + WCHUNKS;  // 12582912
    cvt_both_kernel<<<(int)(total_chunks / 256), 256>>>(
        reinterpret_cast<const float4*>(x), reinterpret_cast<const float4*>(w));

    cudaFuncSetAttribute(gemm_kernel, cudaFuncAttributeMaxDynamicSharedMemorySize,
                         SMEM_B);
    dim3 grid(NDIM / BN, MDIM / BM);  // (16, 64)
    gemm_kernel<<<grid, THREADS, SMEM_B>>>(out);
}

// round 5
// speedup vs baseline: 1.0434x; 1.0093x over previous
#include <cuda_runtime.h>
#include <cuda_fp16.h>
#include <cstdint>
#include <cstddef>

// Problem dims: y[b,m,n] = sum_k x[b,m,k] w[k,n]; flatten b,m -> M
#define MDIM 8192
#define KDIM 4096
#define NDIM 4096

// GEMM tiling: CTA 128x256x64, 16 warps (4m x 4n), warp tile 32x64, 3 stages
#define BM 128
#define BN 256
#define BK 64
#define STAGES 3
#define KT (KDIM / BK)  // 64
#define THREADS 512

#define LDA 72   // 64 + 8 pad (fp16 elems per A smem row)
#define LDB 264  // 256 + 8 pad
#define A_TILE_B (BM * LDA * 2)        // 18432
#define B_TILE_B (BK * LDB * 2)        // 33792
#define STAGE_B (A_TILE_B + B_TILE_B)  // 52224
#define SMEM_B (STAGES * STAGE_B)      // 156672

// fp16 scratch (allocation-free rule: __device__ globals)
__device__ __half g_xh[(size_t)MDIM * KDIM];  // 67 MB
__device__ __half g_wh[(size_t)KDIM * NDIM];  // 33.5 MB

static __device__ __forceinline__ uint32_t smem_u32(const void* p) {
    uint32_t a;
    asm("{ .reg .u64 t; cvta.to.shared.u64 t, %1; cvt.u32.u64 %0, t; }"
        : "=r"(a) : "l"(p));
    return a;
}

#define CP_ASYNC16(dst, src) \
    asm volatile("cp.async.cg.shared.global [%0], [%1], 16;" :: "r"(dst), "l"(src))
#define CP_COMMIT() asm volatile("cp.async.commit_group;" ::: "memory")
#define CP_WAIT(n)  asm volatile("cp.async.wait_group %0;" :: "n"(n) : "memory")

#define LDMATRIX_X4(r0, r1, r2, r3, addr)                                  \
    asm volatile("ldmatrix.sync.aligned.m8n8.x4.shared.b16 "               \
                 "{%0,%1,%2,%3}, [%4];"                                    \
                 : "=r"(r0), "=r"(r1), "=r"(r2), "=r"(r3) : "r"(addr))

#define LDMATRIX_X4_T(r0, r1, r2, r3, addr)                                \
    asm volatile("ldmatrix.sync.aligned.m8n8.x4.trans.shared.b16 "         \
                 "{%0,%1,%2,%3}, [%4];"                                    \
                 : "=r"(r0), "=r"(r1), "=r"(r2), "=r"(r3) : "r"(addr))

#define MMA16816(d, a, b0, b1)                                             \
    asm volatile("mma.sync.aligned.m16n8k16.row.col.f32.f16.f16.f32 "      \
                 "{%0,%1,%2,%3}, {%4,%5,%6,%7}, {%8,%9}, {%0,%1,%2,%3};"   \
                 : "+f"((d)[0]), "+f"((d)[1]), "+f"((d)[2]), "+f"((d)[3])  \
                 : "r"((a)[0]), "r"((a)[1]), "r"((a)[2]), "r"((a)[3]),     \
                   "r"(b0), "r"(b1))

// ---------------------------------------------------------------------------
// prep: fused fp32 -> fp16 for both x and w (one launch)
// ---------------------------------------------------------------------------
#define XCHUNKS ((size_t)MDIM * KDIM / 4)  // 8388608 float4s
#define WCHUNKS ((size_t)KDIM * NDIM / 4)  // 4194304 float4s

__global__ void cvt_both_kernel(const float4* __restrict__ x4,
                                const float4* __restrict__ w4) {
    size_t i = (size_t)blockIdx.x * blockDim.x + threadIdx.x;
    const float4* src;
    uint2* dst;
    if (i < XCHUNKS) {
        src = x4 + i;
        dst = reinterpret_cast<uint2*>(g_xh) + i;
    } else {
        src = w4 + (i - XCHUNKS);
        dst = reinterpret_cast<uint2*>(g_wh) + (i - XCHUNKS);
    }
    float4 v = *src;
    __half2 h0 = __floats2half2_rn(v.x, v.y);
    __half2 h1 = __floats2half2_rn(v.z, v.w);
    uint2 o;
    o.x = *reinterpret_cast<uint32_t*>(&h0);
    o.y = *reinterpret_cast<uint32_t*>(&h1);
    *dst = o;
}

// ---------------------------------------------------------------------------
// GEMM: 16 warps per CTA -> 4 warps/SMSP to overlap LDSM with HMMA
// ---------------------------------------------------------------------------
__global__ void __launch_bounds__(THREADS, 1) gemm_kernel(float* __restrict__ out) {
    extern __shared__ char smem_raw[];
    const uint32_t smem = smem_u32(smem_raw);

    const int tid = threadIdx.x;
    const int lane = tid & 31;
    const int wid = tid >> 5;
    const int warp_m = wid & 3;   // 0..3
    const int warp_n = wid >> 2;  // 0..3

    const int m0 = blockIdx.y * BM;
    const int n0 = blockIdx.x * BN;

    const __half* gA = g_xh + (size_t)m0 * KDIM;
    const __half* gB = g_wh + n0;

    // ---- cp.async addresses: A 1024 chunks (2/thread), B 2048 chunks (4/thread)
    uint32_t sA_dst[2];
    const __half* gA_src[2];
#pragma unroll
    for (int i = 0; i < 2; ++i) {
        int c = tid + i * THREADS;
        int row = c >> 3, ch = c & 7;
        sA_dst[i] = smem + (uint32_t)(row * LDA + ch * 8) * 2;
        gA_src[i] = gA + (size_t)row * KDIM + ch * 8;
    }
    uint32_t sB_dst[4];
    const __half* gB_src[4];
#pragma unroll
    for (int i = 0; i < 4; ++i) {
        int c = tid + i * THREADS;
        int row = c >> 5, ch = c & 31;
        sB_dst[i] = smem + A_TILE_B + (uint32_t)(row * LDB + ch * 8) * 2;
        gB_src[i] = gB + (size_t)row * NDIM + ch * 8;
    }

#define ISSUE_STAGE(slot, kt_)                                              \
    do {                                                                    \
        const uint32_t sb = (uint32_t)(slot) * STAGE_B;                     \
        const size_t kb = (size_t)(kt_) * BK;                               \
        _Pragma("unroll")                                                   \
        for (int i = 0; i < 2; ++i)                                         \
            CP_ASYNC16(sA_dst[i] + sb, gA_src[i] + kb);                     \
        _Pragma("unroll")                                                   \
        for (int i = 0; i < 4; ++i)                                         \
            CP_ASYNC16(sB_dst[i] + sb, gB_src[i] + kb * NDIM);              \
    } while (0)

    // ---- fragment base addresses ----
    // A x4 (16 rows x 16 k): rows warp_m*32 + mi*16 + (lane&15), k-col (lane>>4)*8
    const uint32_t a_frag =
        smem + (uint32_t)((warp_m * 32 + (lane & 15)) * LDA + (lane >> 4) * 8) * 2;
    // B x4.trans (16 k x 16 n): k-rows (lane&15), n-col warp_n*64 + (lane>>4)*8
    const uint32_t b_frag =
        smem + A_TILE_B +
        (uint32_t)((lane & 15) * LDB + warp_n * 64 + (lane >> 4) * 8) * 2;

    float acc[2][8][4];
#pragma unroll
    for (int mi = 0; mi < 2; ++mi)
#pragma unroll
        for (int ni = 0; ni < 8; ++ni)
#pragma unroll
            for (int q = 0; q < 4; ++q) acc[mi][ni][q] = 0.f;

    // ---- prologue ----
#pragma unroll
    for (int s = 0; s < STAGES - 1; ++s) {
        ISSUE_STAGE(s, s);
        CP_COMMIT();
    }

    // ---- mainloop ----
    int s_cur = 0;
    int s_nxt = STAGES - 1;
    for (int kt = 0; kt < KT; ++kt) {
        CP_WAIT(STAGES - 2);
        __syncthreads();

        if (kt + STAGES - 1 < KT) ISSUE_STAGE(s_nxt, kt + STAGES - 1);
        CP_COMMIT();

        const uint32_t sb = (uint32_t)s_cur * STAGE_B;
        const uint32_t aB = a_frag + sb;
        const uint32_t bB = b_frag + sb;

#pragma unroll
        for (int kk = 0; kk < 4; ++kk) {
            uint32_t a[2][4], b[4][4];
#pragma unroll
            for (int mi = 0; mi < 2; ++mi)
                LDMATRIX_X4(a[mi][0], a[mi][1], a[mi][2], a[mi][3],
                            aB + (uint32_t)(mi * 16 * LDA + kk * 16) * 2);
#pragma unroll
            for (int nj = 0; nj < 4; ++nj)
                LDMATRIX_X4_T(b[nj][0], b[nj][1], b[nj][2], b[nj][3],
                              bB + (uint32_t)(kk * 16 * LDB + nj * 16) * 2);
            // b[nj] = {b0(n+0), b1(n+0), b0(n+8), b1(n+8)}
#pragma unroll
            for (int mi = 0; mi < 2; ++mi)
#pragma unroll
                for (int nj = 0; nj < 4; ++nj) {
                    MMA16816(acc[mi][2 * nj + 0], a[mi], b[nj][0], b[nj][1]);
                    MMA16816(acc[mi][2 * nj + 1], a[mi], b[nj][2], b[nj][3]);
                }
        }
        if (++s_cur == STAGES) s_cur = 0;
        if (++s_nxt == STAGES) s_nxt = 0;
    }

    // ---- epilogue: direct fp32 stores ----
    const int mg = m0 + warp_m * 32 + (lane >> 2);
    const int ng = n0 + warp_n * 64 + (lane & 3) * 2;
#pragma unroll
    for (int mi = 0; mi < 2; ++mi) {
#pragma unroll
        for (int ni = 0; ni < 8; ++ni) {
            float* p0 = out + (size_t)(mg + mi * 16) * NDIM + ng + ni * 8;
            float* p1 = p0 + 8 * NDIM;
            *reinterpret_cast<float2*>(p0) = make_float2(acc[mi][ni][0], acc[mi][ni][1]);
            *reinterpret_cast<float2*>(p1) = make_float2(acc[mi][ni][2], acc[mi][ni][3]);
        }
    }
}

// ---------------------------------------------------------------------------
extern "C" void kernel_launch(void* const* d_in, const int* in_sizes, int n_in,
                              void* d_out, int out_size) {
    const float* x = (const float*)d_in[0];  // (4, 2048, 4096) fp32
    const float* w = (const float*)d_in[1];  // (4096, 4096) fp32 ternary
    float* out = (float*)d_out;              // (4, 2048, 4096) fp32

    size_t total_chunks = XCHUNKS + WCHUNKS;  // 12582912
    cvt_both_kernel<<<(int)(total_chunks / 256), 256>>>(
        reinterpret_cast<const float4*>(x), reinterpret_cast<const float4*>(w));

    cudaFuncSetAttribute(gemm_kernel, cudaFuncAttributeMaxDynamicSharedMemorySize,
                         SMEM_B);
    dim3 grid(NDIM / BN, MDIM / BM);  // (16, 64)
    gemm_kernel<<<grid, THREADS, SMEM_B>>>(out);
}

// round 6
// speedup vs baseline: 1.1244x; 1.0776x over previous
#include <cuda_runtime.h>
#include <cuda_fp16.h>
#include <cstdint>
#include <cstddef>

// Problem dims: y[b,m,n] = sum_k x[b,m,k] w[k,n]; flatten b,m -> M
#define MDIM 8192
#define KDIM 4096
#define NDIM 4096

// GEMM tiling: CTA 128x128x64, 8 warps (2m x 4n), warp tile 64x32, 3 stages
// smem 107.5KB -> 2 CTAs/SM for cross-CTA phase overlap
#define BM 128
#define BN 128
#define BK 64
#define STAGES 3
#define KT (KDIM / BK)  // 64
#define THREADS 256

#define LDA 72   // 64 + 8 pad (fp16 elems per A smem row)
#define LDB 136  // 128 + 8 pad
#define A_TILE_B (BM * LDA * 2)        // 18432
#define B_TILE_B (BK * LDB * 2)        // 17408
#define STAGE_B (A_TILE_B + B_TILE_B)  // 35840
#define SMEM_B (STAGES * STAGE_B)      // 107520

// fp16 scratch (allocation-free rule: __device__ globals)
__device__ __half g_xh[(size_t)MDIM * KDIM];  // 67 MB
__device__ __half g_wh[(size_t)KDIM * NDIM];  // 33.5 MB

static __device__ __forceinline__ uint32_t smem_u32(const void* p) {
    uint32_t a;
    asm("{ .reg .u64 t; cvta.to.shared.u64 t, %1; cvt.u32.u64 %0, t; }"
        : "=r"(a) : "l"(p));
    return a;
}

#define CP_ASYNC16(dst, src) \
    asm volatile("cp.async.cg.shared.global [%0], [%1], 16;" :: "r"(dst), "l"(src))
#define CP_COMMIT() asm volatile("cp.async.commit_group;" ::: "memory")
#define CP_WAIT(n)  asm volatile("cp.async.wait_group %0;" :: "n"(n) : "memory")

#define LDMATRIX_X4(r0, r1, r2, r3, addr)                                  \
    asm volatile("ldmatrix.sync.aligned.m8n8.x4.shared.b16 "               \
                 "{%0,%1,%2,%3}, [%4];"                                    \
                 : "=r"(r0), "=r"(r1), "=r"(r2), "=r"(r3) : "r"(addr))

#define LDMATRIX_X4_T(r0, r1, r2, r3, addr)                                \
    asm volatile("ldmatrix.sync.aligned.m8n8.x4.trans.shared.b16 "         \
                 "{%0,%1,%2,%3}, [%4];"                                    \
                 : "=r"(r0), "=r"(r1), "=r"(r2), "=r"(r3) : "r"(addr))

#define MMA16816(d, a, b0, b1)                                             \
    asm volatile("mma.sync.aligned.m16n8k16.row.col.f32.f16.f16.f32 "      \
                 "{%0,%1,%2,%3}, {%4,%5,%6,%7}, {%8,%9}, {%0,%1,%2,%3};"   \
                 : "+f"((d)[0]), "+f"((d)[1]), "+f"((d)[2]), "+f"((d)[3])  \
                 : "r"((a)[0]), "r"((a)[1]), "r"((a)[2]), "r"((a)[3]),     \
                   "r"(b0), "r"(b1))

// ---------------------------------------------------------------------------
// prep: fused fp32 -> fp16 for both x and w (one launch)
// ---------------------------------------------------------------------------
#define XCHUNKS ((size_t)MDIM * KDIM / 4)  // 8388608 float4s
#define WCHUNKS ((size_t)KDIM * NDIM / 4)  // 4194304 float4s

__global__ void cvt_both_kernel(const float4* __restrict__ x4,
                                const float4* __restrict__ w4) {
    size_t i = (size_t)blockIdx.x * blockDim.x + threadIdx.x;
    const float4* src;
    uint2* dst;
    if (i < XCHUNKS) {
        src = x4 + i;
        dst = reinterpret_cast<uint2*>(g_xh) + i;
    } else {
        src = w4 + (i - XCHUNKS);
        dst = reinterpret_cast<uint2*>(g_wh) + (i - XCHUNKS);
    }
    float4 v = *src;
    __half2 h0 = __floats2half2_rn(v.x, v.y);
    __half2 h1 = __floats2half2_rn(v.z, v.w);
    uint2 o;
    o.x = *reinterpret_cast<uint32_t*>(&h0);
    o.y = *reinterpret_cast<uint32_t*>(&h1);
    *dst = o;
}

// ---------------------------------------------------------------------------
// GEMM: 2 CTAs/SM; barrier/LDSM window of one CTA hides under the other's MMAs
// ---------------------------------------------------------------------------
__global__ void __launch_bounds__(THREADS, 2) gemm_kernel(float* __restrict__ out) {
    extern __shared__ char smem_raw[];
    const uint32_t smem = smem_u32(smem_raw);

    const int tid = threadIdx.x;
    const int lane = tid & 31;
    const int wid = tid >> 5;
    const int warp_m = wid & 1;   // 0..1
    const int warp_n = wid >> 1;  // 0..3

    const int m0 = blockIdx.y * BM;
    const int n0 = blockIdx.x * BN;

    const __half* gA = g_xh + (size_t)m0 * KDIM;
    const __half* gB = g_wh + n0;

    // ---- cp.async addresses: A 1024 chunks (4/thread), B 1024 chunks (4/thread)
    uint32_t sA_dst[4];
    const __half* gA_src[4];
#pragma unroll
    for (int i = 0; i < 4; ++i) {
        int c = tid + i * THREADS;
        int row = c >> 3, ch = c & 7;
        sA_dst[i] = smem + (uint32_t)(row * LDA + ch * 8) * 2;
        gA_src[i] = gA + (size_t)row * KDIM + ch * 8;
    }
    uint32_t sB_dst[4];
    const __half* gB_src[4];
#pragma unroll
    for (int i = 0; i < 4; ++i) {
        int c = tid + i * THREADS;
        int row = c >> 4, ch = c & 15;
        sB_dst[i] = smem + A_TILE_B + (uint32_t)(row * LDB + ch * 8) * 2;
        gB_src[i] = gB + (size_t)row * NDIM + ch * 8;
    }

#define ISSUE_STAGE(slot, kt_)                                              \
    do {                                                                    \
        const uint32_t sb = (uint32_t)(slot) * STAGE_B;                     \
        const size_t kb = (size_t)(kt_) * BK;                               \
        _Pragma("unroll")                                                   \
        for (int i = 0; i < 4; ++i)                                         \
            CP_ASYNC16(sA_dst[i] + sb, gA_src[i] + kb);                     \
        _Pragma("unroll")                                                   \
        for (int i = 0; i < 4; ++i)                                         \
            CP_ASYNC16(sB_dst[i] + sb, gB_src[i] + kb * NDIM);              \
    } while (0)

    // ---- fragment base addresses ----
    // A x4: rows warp_m*64 + mi*16 + (lane&15), k-col (lane>>4)*8
    const uint32_t a_frag =
        smem + (uint32_t)((warp_m * 64 + (lane & 15)) * LDA + (lane >> 4) * 8) * 2;
    // B x4.trans: k-rows (lane&15), n-col warp_n*32 + (lane>>4)*8
    const uint32_t b_frag =
        smem + A_TILE_B +
        (uint32_t)((lane & 15) * LDB + warp_n * 32 + (lane >> 4) * 8) * 2;

    float acc[4][4][4];
#pragma unroll
    for (int mi = 0; mi < 4; ++mi)
#pragma unroll
        for (int ni = 0; ni < 4; ++ni)
#pragma unroll
            for (int q = 0; q < 4; ++q) acc[mi][ni][q] = 0.f;

    // ---- prologue ----
#pragma unroll
    for (int s = 0; s < STAGES - 1; ++s) {
        ISSUE_STAGE(s, s);
        CP_COMMIT();
    }

    // ---- mainloop ----
    int s_cur = 0;
    int s_nxt = STAGES - 1;
    for (int kt = 0; kt < KT; ++kt) {
        CP_WAIT(STAGES - 2);
        __syncthreads();

        if (kt + STAGES - 1 < KT) ISSUE_STAGE(s_nxt, kt + STAGES - 1);
        CP_COMMIT();

        const uint32_t sb = (uint32_t)s_cur * STAGE_B;
        const uint32_t aB = a_frag + sb;
        const uint32_t bB = b_frag + sb;

#pragma unroll
        for (int kk = 0; kk < 4; ++kk) {
            uint32_t a[4][4], b[2][4];
#pragma unroll
            for (int mi = 0; mi < 4; ++mi)
                LDMATRIX_X4(a[mi][0], a[mi][1], a[mi][2], a[mi][3],
                            aB + (uint32_t)(mi * 16 * LDA + kk * 16) * 2);
#pragma unroll
            for (int nj = 0; nj < 2; ++nj)
                LDMATRIX_X4_T(b[nj][0], b[nj][1], b[nj][2], b[nj][3],
                              bB + (uint32_t)(kk * 16 * LDB + nj * 16) * 2);
            // b[nj] = {b0(n+0), b1(n+0), b0(n+8), b1(n+8)}
#pragma unroll
            for (int mi = 0; mi < 4; ++mi)
#pragma unroll
                for (int nj = 0; nj < 2; ++nj) {
                    MMA16816(acc[mi][2 * nj + 0], a[mi], b[nj][0], b[nj][1]);
                    MMA16816(acc[mi][2 * nj + 1], a[mi], b[nj][2], b[nj][3]);
                }
        }
        if (++s_cur == STAGES) s_cur = 0;
        if (++s_nxt == STAGES) s_nxt = 0;
    }

    // ---- epilogue: direct fp32 stores ----
    const int mg = m0 + warp_m * 64 + (lane >> 2);
    const int ng = n0 + warp_n * 32 + (lane & 3) * 2;
#pragma unroll
    for (int mi = 0; mi < 4; ++mi) {
#pragma unroll
        for (int ni = 0; ni < 4; ++ni) {
            float* p0 = out + (size_t)(mg + mi * 16) * NDIM + ng + ni * 8;
            float* p1 = p0 + 8 * NDIM;
            *reinterpret_cast<float2*>(p0) = make_float2(acc[mi][ni][0], acc[mi][ni][1]);
            *reinterpret_cast<float2*>(p1) = make_float2(acc[mi][ni][2], acc[mi][ni][3]);
        }
    }
}

// ---------------------------------------------------------------------------
extern "C" void kernel_launch(void* const* d_in, const int* in_sizes, int n_in,
                              void* d_out, int out_size) {
    const float* x = (const float*)d_in[0];  // (4, 2048, 4096) fp32
    const float* w = (const float*)d_in[1];  // (4096, 4096) fp32 ternary
    float* out = (float*)d_out;              // (4, 2048, 4096) fp32

    size_t total_chunks = XCHUNKS + WCHUNKS;  // 12582912
    cvt_both_kernel<<<(int)(total_chunks / 256), 256>>>(
        reinterpret_cast<const float4*>(x), reinterpret_cast<const float4*>(w));

    cudaFuncSetAttribute(gemm_kernel, cudaFuncAttributeMaxDynamicSharedMemorySize,
                         SMEM_B);
    dim3 grid(NDIM / BN, MDIM / BM);  // (32, 64)
    gemm_kernel<<<grid, THREADS, SMEM_B>>>(out);
}